// round 1
// baseline (speedup 1.0000x reference)
#include <cuda_runtime.h>
#include <cstdint>

#define NN   10000
#define EE   320000
#define FIN  512
#define NHID 32
#define LAT  16
#define PAD  128   // max in-degree padding (Binomial(320000,1e-4): mean 32, max ~55)

// ---------------- device scratch (no allocations allowed) ----------------
__device__ int   g_cnt[NN];
__device__ int   g_src[NN * PAD];
__device__ float g_wgt[NN * PAD];
__device__ float g_h0 [NN * NHID];
__device__ float g_h  [NN * NHID];
__device__ float g_z0 [NN * LAT];

// ---------------- adjacency build (padded CSR-like, gather-friendly) -----
__global__ void k_zero() {
    int i = blockIdx.x * blockDim.x + threadIdx.x;
    if (i < NN) g_cnt[i] = 0;
}

__global__ void k_build(const int* __restrict__ ei, const float* __restrict__ ew) {
    int e = blockIdx.x * blockDim.x + threadIdx.x;
    if (e >= EE) return;
    int   s = ei[e];
    int   d = ei[EE + e];
    float w = ew[e];
    int p = atomicAdd(&g_cnt[d], 1);
    if (p < PAD) {
        g_src[d * PAD + p] = s;
        g_wgt[d * PAD + p] = w;
    }
}

// ---------------- GEMM1: h0[N,32] = x[N,512] @ W1[512,32] ----------------
// 256 threads, 64 rows per block, k-chunks of 16 staged in shared.
// Thread computes 2 rows x 4 cols.
__global__ void __launch_bounds__(256) k_gemm1(const float* __restrict__ x,
                                               const float* __restrict__ W1) {
    __shared__ float xs[64][28];   // pad 28 floats (112B, 16B-aligned) — conflict-free
    __shared__ float w1s[16][32];

    int t    = threadIdx.x;
    int row0 = blockIdx.x * 64;
    int cg   = (t & 7) << 2;        // col group: cg..cg+3
    int rs   = (t >> 3) << 1;       // row pair: rs, rs+1

    float acc00=0.f, acc01=0.f, acc02=0.f, acc03=0.f;
    float acc10=0.f, acc11=0.f, acc12=0.f, acc13=0.f;

    for (int kk = 0; kk < FIN; kk += 16) {
        // stage x chunk: 64 rows x 16 k = 256 float4
        {
            int r  = t >> 2;
            int kq = (t & 3) << 2;
            int gr = row0 + r;
            float4 v = make_float4(0.f, 0.f, 0.f, 0.f);
            if (gr < NN) v = *(const float4*)(x + (size_t)gr * FIN + kk + kq);
            *(float4*)&xs[r][kq] = v;
        }
        // stage W1 chunk: 16 x 32 = 128 float4
        if (t < 128) {
            int k = t >> 3, c = (t & 7) << 2;
            *(float4*)&w1s[k][c] = *(const float4*)(W1 + (size_t)(kk + k) * NHID + c);
        }
        __syncthreads();

        #pragma unroll
        for (int k = 0; k < 16; k++) {
            float4 b = *(const float4*)&w1s[k][cg];
            float a0 = xs[rs][k];
            float a1 = xs[rs + 1][k];
            acc00 = fmaf(a0, b.x, acc00); acc01 = fmaf(a0, b.y, acc01);
            acc02 = fmaf(a0, b.z, acc02); acc03 = fmaf(a0, b.w, acc03);
            acc10 = fmaf(a1, b.x, acc10); acc11 = fmaf(a1, b.y, acc11);
            acc12 = fmaf(a1, b.z, acc12); acc13 = fmaf(a1, b.w, acc13);
        }
        __syncthreads();
    }

    int gr0 = row0 + rs;
    if (gr0 < NN)
        *(float4*)&g_h0[(size_t)gr0 * NHID + cg] = make_float4(acc00, acc01, acc02, acc03);
    if (gr0 + 1 < NN)
        *(float4*)&g_h0[(size_t)(gr0 + 1) * NHID + cg] = make_float4(acc10, acc11, acc12, acc13);
}

// ---------------- SpMM1: h[d,:] = sum_e w_e * h0[src_e,:]  (32 cols) -----
// One warp per destination node; lane = column.
__global__ void k_spmm1() {
    int gid  = blockIdx.x * blockDim.x + threadIdx.x;
    int d    = gid >> 5;
    int lane = gid & 31;
    if (d >= NN) return;
    int cnt = g_cnt[d];
    if (cnt > PAD) cnt = PAD;
    const int*   sp = &g_src[d * PAD];
    const float* wp = &g_wgt[d * PAD];
    float acc = 0.f;
    #pragma unroll 4
    for (int j = 0; j < cnt; j++) {
        int   s = sp[j];
        float w = wp[j];
        acc = fmaf(w, g_h0[(size_t)s * NHID + lane], acc);
    }
    g_h[(size_t)d * NHID + lane] = acc;
}

// ---------------- GEMM2: z0[N,16] = h[N,32] @ W2[32,16] ------------------
__global__ void k_gemm2(const float* __restrict__ W2) {
    __shared__ float w2s[NHID * LAT];
    int t = threadIdx.x;
    for (int i = t; i < NHID * LAT; i += 256) w2s[i] = W2[i];
    __syncthreads();

    int row = blockIdx.x * 256 + t;
    if (row >= NN) return;

    float hr[NHID];
    #pragma unroll
    for (int q = 0; q < NHID / 4; q++) {
        float4 v = *(const float4*)&g_h[(size_t)row * NHID + q * 4];
        hr[q * 4 + 0] = v.x; hr[q * 4 + 1] = v.y;
        hr[q * 4 + 2] = v.z; hr[q * 4 + 3] = v.w;
    }
    #pragma unroll
    for (int c = 0; c < LAT; c++) {
        float acc = 0.f;
        #pragma unroll
        for (int k = 0; k < NHID; k++)
            acc = fmaf(hr[k], w2s[k * LAT + c], acc);
        g_z0[(size_t)row * LAT + c] = acc;
    }
}

// ---------------- SpMM2: z[d,:] = sum_e w_e * z0[src_e,:]  (16 cols) -----
// 16 threads per destination node.
__global__ void k_spmm2(float* __restrict__ zout) {
    int gid = blockIdx.x * blockDim.x + threadIdx.x;
    int d   = gid >> 4;
    int c   = gid & 15;
    if (d >= NN) return;
    int cnt = g_cnt[d];
    if (cnt > PAD) cnt = PAD;
    const int*   sp = &g_src[d * PAD];
    const float* wp = &g_wgt[d * PAD];
    float acc = 0.f;
    #pragma unroll 4
    for (int j = 0; j < cnt; j++) {
        int   s = sp[j];
        float w = wp[j];
        acc = fmaf(w, g_z0[(size_t)s * LAT + c], acc);
    }
    zout[(size_t)d * LAT + c] = acc;
}

// ---------------- Decoder: adj = sigmoid(z @ z^T), [10000 x 10000] -------
__device__ __forceinline__ float sigmoid_fast(float x) {
    float t;
    asm("tanh.approx.f32 %0, %1;" : "=f"(t) : "f"(0.5f * x));
    return fmaf(0.5f, t, 0.5f);
}

// 128x128 tile per 256-thread block; each thread 8i x 8j register tile.
// zjs is k-major (padded to 132) so per-k zj fragments are 2x LDS.128,
// conflict-free; zi reads are broadcast scalars.
__global__ void __launch_bounds__(256, 2) k_dec(const float* __restrict__ z,
                                                float* __restrict__ out) {
    __shared__ float zis[128][16];
    __shared__ float zjs[16][132];
    int t  = threadIdx.x;
    int i0 = blockIdx.y * 128;
    int j0 = blockIdx.x * 128;

    #pragma unroll
    for (int rep = 0; rep < 2; rep++) {
        int idx = t + rep * 256;
        int r  = idx >> 2;
        int kq = (idx & 3) << 2;
        int gi = i0 + r;
        float4 v = make_float4(0.f, 0.f, 0.f, 0.f);
        if (gi < NN) v = *(const float4*)(z + (size_t)gi * LAT + kq);
        *(float4*)&zis[r][kq] = v;

        int gj = j0 + r;
        float4 u = make_float4(0.f, 0.f, 0.f, 0.f);
        if (gj < NN) u = *(const float4*)(z + (size_t)gj * LAT + kq);
        zjs[kq + 0][r] = u.x; zjs[kq + 1][r] = u.y;
        zjs[kq + 2][r] = u.z; zjs[kq + 3][r] = u.w;
    }
    __syncthreads();

    int tx = t & 15, ty = t >> 4;
    int ib = ty * 8, jb = tx * 8;

    float acc[8][8];
    #pragma unroll
    for (int r = 0; r < 8; r++)
        #pragma unroll
        for (int c = 0; c < 8; c++) acc[r][c] = 0.f;

    #pragma unroll
    for (int k = 0; k < 16; k++) {
        float4 b0 = *(const float4*)&zjs[k][jb];
        float4 b1 = *(const float4*)&zjs[k][jb + 4];
        #pragma unroll
        for (int r = 0; r < 8; r++) {
            float a = zis[ib + r][k];
            acc[r][0] = fmaf(a, b0.x, acc[r][0]);
            acc[r][1] = fmaf(a, b0.y, acc[r][1]);
            acc[r][2] = fmaf(a, b0.z, acc[r][2]);
            acc[r][3] = fmaf(a, b0.w, acc[r][3]);
            acc[r][4] = fmaf(a, b1.x, acc[r][4]);
            acc[r][5] = fmaf(a, b1.y, acc[r][5]);
            acc[r][6] = fmaf(a, b1.z, acc[r][6]);
            acc[r][7] = fmaf(a, b1.w, acc[r][7]);
        }
    }

    int gj = j0 + jb;
    #pragma unroll
    for (int r = 0; r < 8; r++) {
        int gi = i0 + ib + r;
        if (gi < NN && gj < NN) {   // NN % 8 == 0 at tile edges -> whole group valid
            float4 o0, o1;
            o0.x = sigmoid_fast(acc[r][0]); o0.y = sigmoid_fast(acc[r][1]);
            o0.z = sigmoid_fast(acc[r][2]); o0.w = sigmoid_fast(acc[r][3]);
            o1.x = sigmoid_fast(acc[r][4]); o1.y = sigmoid_fast(acc[r][5]);
            o1.z = sigmoid_fast(acc[r][6]); o1.w = sigmoid_fast(acc[r][7]);
            float* p = out + (size_t)gi * NN + gj;
            *(float4*)p       = o0;
            *(float4*)(p + 4) = o1;
        }
    }
}

// ---------------- launch --------------------------------------------------
extern "C" void kernel_launch(void* const* d_in, const int* in_sizes, int n_in,
                              void* d_out, int out_size) {
    const float* x  = (const float*)d_in[0];
    const float* W1 = (const float*)d_in[1];
    const float* W2 = (const float*)d_in[2];
    const int*   ei = (const int*)  d_in[3];
    const float* ew = (const float*)d_in[4];

    float* out  = (float*)d_out;
    float* zout = out + (size_t)NN * NN;   // output layout: [adj (1e8) | z (160000)]

    k_zero <<<(NN + 255) / 256, 256>>>();
    k_build<<<(EE + 255) / 256, 256>>>(ei, ew);
    k_gemm1<<<(NN + 63) / 64, 256>>>(x, W1);
    k_spmm1<<<(NN * 32 + 255) / 256, 256>>>();
    k_gemm2<<<(NN + 255) / 256, 256>>>(W2);
    k_spmm2<<<(NN * 16 + 255) / 256, 256>>>(zout);

    dim3 gdec((NN + 127) / 128, (NN + 127) / 128);
    k_dec<<<gdec, 256>>>(zout, out);
}

// round 2
// speedup vs baseline: 1.0365x; 1.0365x over previous
#include <cuda_runtime.h>
#include <cstdint>

#define NN   10000
#define EE   320000
#define FIN  512
#define NHID 32
#define LAT  16
#define PAD  128

typedef unsigned long long u64;

// ---------------- device scratch (no allocations allowed) ----------------
__device__ int   g_cnt[NN];
__device__ int   g_src[NN * PAD];
__device__ float g_wgt[NN * PAD];
__device__ float g_h0 [NN * NHID];
__device__ float g_h  [NN * NHID];
__device__ float g_z0 [NN * LAT];

// ---------------- f32x2 packed helpers (sm_103a FFMA2 path) --------------
__device__ __forceinline__ u64 fma2(u64 a, u64 b, u64 c) {
    u64 d;
    asm("fma.rn.f32x2 %0, %1, %2, %3;" : "=l"(d) : "l"(a), "l"(b), "l"(c));
    return d;
}
__device__ __forceinline__ u64 pack2(float x) {
    u64 d; asm("mov.b64 %0, {%1, %1};" : "=l"(d) : "f"(x)); return d;
}
__device__ __forceinline__ float lo2(u64 v) {
    float f; asm("{ .reg .f32 h; mov.b64 {%0, h}, %1; }" : "=f"(f) : "l"(v)); return f;
}
__device__ __forceinline__ float hi2(u64 v) {
    float f; asm("{ .reg .f32 l; mov.b64 {l, %0}, %1; }" : "=f"(f) : "l"(v)); return f;
}
__device__ __forceinline__ float sigmoid_fast(float x) {
    float t;
    asm("tanh.approx.f32 %0, %1;" : "=f"(t) : "f"(0.5f * x));
    return fmaf(0.5f, t, 0.5f);
}
__device__ __forceinline__ u64 sig2(u64 x) {
    float lo = sigmoid_fast(lo2(x));
    float hi = sigmoid_fast(hi2(x));
    u64 r; asm("mov.b64 %0, {%1, %2};" : "=l"(r) : "f"(lo), "f"(hi));
    return r;
}

// ---------------- adjacency build (padded, gather-friendly) --------------
__global__ void k_zero() {
    int i = blockIdx.x * blockDim.x + threadIdx.x;
    if (i < NN) g_cnt[i] = 0;
}

__global__ void k_build(const int* __restrict__ ei, const float* __restrict__ ew) {
    int e = blockIdx.x * blockDim.x + threadIdx.x;
    if (e >= EE) return;
    int   s = ei[e];
    int   d = ei[EE + e];
    float w = ew[e];
    int p = atomicAdd(&g_cnt[d], 1);
    if (p < PAD) {
        g_src[d * PAD + p] = s;
        g_wgt[d * PAD + p] = w;
    }
}

// ---------------- GEMM1: h0[N,32] = x[N,512] @ W1[512,32] ----------------
__global__ void __launch_bounds__(256) k_gemm1(const float* __restrict__ x,
                                               const float* __restrict__ W1) {
    __shared__ float xs[64][28];
    __shared__ float w1s[16][32];

    int t    = threadIdx.x;
    int row0 = blockIdx.x * 64;
    int cg   = (t & 7) << 2;
    int rs   = (t >> 3) << 1;

    float acc00=0.f, acc01=0.f, acc02=0.f, acc03=0.f;
    float acc10=0.f, acc11=0.f, acc12=0.f, acc13=0.f;

    for (int kk = 0; kk < FIN; kk += 16) {
        {
            int r  = t >> 2;
            int kq = (t & 3) << 2;
            int gr = row0 + r;
            float4 v = make_float4(0.f, 0.f, 0.f, 0.f);
            if (gr < NN) v = *(const float4*)(x + (size_t)gr * FIN + kk + kq);
            *(float4*)&xs[r][kq] = v;
        }
        if (t < 128) {
            int k = t >> 3, c = (t & 7) << 2;
            *(float4*)&w1s[k][c] = *(const float4*)(W1 + (size_t)(kk + k) * NHID + c);
        }
        __syncthreads();

        #pragma unroll
        for (int k = 0; k < 16; k++) {
            float4 b = *(const float4*)&w1s[k][cg];
            float a0 = xs[rs][k];
            float a1 = xs[rs + 1][k];
            acc00 = fmaf(a0, b.x, acc00); acc01 = fmaf(a0, b.y, acc01);
            acc02 = fmaf(a0, b.z, acc02); acc03 = fmaf(a0, b.w, acc03);
            acc10 = fmaf(a1, b.x, acc10); acc11 = fmaf(a1, b.y, acc11);
            acc12 = fmaf(a1, b.z, acc12); acc13 = fmaf(a1, b.w, acc13);
        }
        __syncthreads();
    }

    int gr0 = row0 + rs;
    if (gr0 < NN)
        *(float4*)&g_h0[(size_t)gr0 * NHID + cg] = make_float4(acc00, acc01, acc02, acc03);
    if (gr0 + 1 < NN)
        *(float4*)&g_h0[(size_t)(gr0 + 1) * NHID + cg] = make_float4(acc10, acc11, acc12, acc13);
}

// ---------------- SpMM1: warp per node, 8-wide gather prefetch -----------
__global__ void __launch_bounds__(256) k_spmm1() {
    int gid  = blockIdx.x * blockDim.x + threadIdx.x;
    int d    = gid >> 5;
    int lane = gid & 31;
    if (d >= NN) return;
    int cnt = g_cnt[d];
    if (cnt > PAD) cnt = PAD;
    const int*   sp = &g_src[d * PAD];
    const float* wp = &g_wgt[d * PAD];
    float acc = 0.f;
    int j = 0;
    for (; j + 8 <= cnt; j += 8) {
        int s[8]; float w[8]; float v[8];
        #pragma unroll
        for (int u = 0; u < 8; u++) { s[u] = sp[j + u]; w[u] = wp[j + u]; }
        #pragma unroll
        for (int u = 0; u < 8; u++) v[u] = g_h0[((size_t)s[u] << 5) + lane];
        #pragma unroll
        for (int u = 0; u < 8; u++) acc = fmaf(w[u], v[u], acc);
    }
    for (; j < cnt; j++)
        acc = fmaf(wp[j], g_h0[((size_t)sp[j] << 5) + lane], acc);
    g_h[((size_t)d << 5) + lane] = acc;
}

// ---------------- GEMM2: z0[N,16] = h[N,32] @ W2[32,16] ------------------
__global__ void k_gemm2(const float* __restrict__ W2) {
    __shared__ float w2s[NHID * LAT];
    int t = threadIdx.x;
    for (int i = t; i < NHID * LAT; i += 256) w2s[i] = W2[i];
    __syncthreads();

    int row = blockIdx.x * 256 + t;
    if (row >= NN) return;

    float hr[NHID];
    #pragma unroll
    for (int q = 0; q < NHID / 4; q++) {
        float4 v = *(const float4*)&g_h[(size_t)row * NHID + q * 4];
        hr[q * 4 + 0] = v.x; hr[q * 4 + 1] = v.y;
        hr[q * 4 + 2] = v.z; hr[q * 4 + 3] = v.w;
    }
    #pragma unroll
    for (int c = 0; c < LAT; c++) {
        float acc = 0.f;
        #pragma unroll
        for (int k = 0; k < NHID; k++)
            acc = fmaf(hr[k], w2s[k * LAT + c], acc);
        g_z0[(size_t)row * LAT + c] = acc;
    }
}

// ---------------- SpMM2: 16 threads per node, 8-wide prefetch ------------
__global__ void __launch_bounds__(256) k_spmm2(float* __restrict__ zout) {
    int gid = blockIdx.x * blockDim.x + threadIdx.x;
    int d   = gid >> 4;
    int c   = gid & 15;
    if (d >= NN) return;
    int cnt = g_cnt[d];
    if (cnt > PAD) cnt = PAD;
    const int*   sp = &g_src[d * PAD];
    const float* wp = &g_wgt[d * PAD];
    float acc = 0.f;
    int j = 0;
    for (; j + 8 <= cnt; j += 8) {
        int s[8]; float w[8]; float v[8];
        #pragma unroll
        for (int u = 0; u < 8; u++) { s[u] = sp[j + u]; w[u] = wp[j + u]; }
        #pragma unroll
        for (int u = 0; u < 8; u++) v[u] = g_z0[((size_t)s[u] << 4) + c];
        #pragma unroll
        for (int u = 0; u < 8; u++) acc = fmaf(w[u], v[u], acc);
    }
    for (; j < cnt; j++)
        acc = fmaf(wp[j], g_z0[((size_t)sp[j] << 4) + c], acc);
    zout[((size_t)d << 4) + c] = acc;
}

// ---------------- Decoder: adj = sigmoid(z @ z^T), symmetric -------------
// Upper-triangular 128x128 tiles only; off-diagonal tiles mirror-written
// via a shared-memory transpose (two 64-row passes, smem union'd with the
// input tiles). Inner product uses packed fma.rn.f32x2 (FFMA2): zi rows
// are staged pre-duplicated as (a,a) u64 pairs; zj tile is k-major so the
// 8 j-columns load as two LDS.128 = four f32x2 operands.
__global__ void __launch_bounds__(256) k_dec(const float* __restrict__ z,
                                             float* __restrict__ out) {
    int bi = blockIdx.y, bj = blockIdx.x;
    if (bj < bi) return;                 // lower triangle handled by mirror

    __shared__ union SmU {
        struct {
            u64   zis[128][16];          // packed (a,a) pairs, 16 KB
            float zjs[16][132];          // k-major, padded   8.25 KB
        } in;
        float ts[64][132];               // transpose staging 33.8 KB
    } sm;

    int t  = threadIdx.x;
    int i0 = bi * 128;
    int j0 = bj * 128;

    #pragma unroll
    for (int rep = 0; rep < 2; rep++) {
        int idx = t + rep * 256;
        int r   = idx >> 2;
        int kq  = (idx & 3) << 2;
        int gi  = i0 + r;
        float4 v = make_float4(0.f, 0.f, 0.f, 0.f);
        if (gi < NN) v = *(const float4*)(z + (size_t)gi * LAT + kq);
        sm.in.zis[r][kq + 0] = pack2(v.x);
        sm.in.zis[r][kq + 1] = pack2(v.y);
        sm.in.zis[r][kq + 2] = pack2(v.z);
        sm.in.zis[r][kq + 3] = pack2(v.w);

        int gj = j0 + r;
        float4 u = make_float4(0.f, 0.f, 0.f, 0.f);
        if (gj < NN) u = *(const float4*)(z + (size_t)gj * LAT + kq);
        sm.in.zjs[kq + 0][r] = u.x; sm.in.zjs[kq + 1][r] = u.y;
        sm.in.zjs[kq + 2][r] = u.z; sm.in.zjs[kq + 3][r] = u.w;
    }
    __syncthreads();

    int tx = t & 15, ty = t >> 4;
    int ib = ty << 3, jb = tx << 3;

    u64 acc2[8][4];
    #pragma unroll
    for (int r = 0; r < 8; r++)
        #pragma unroll
        for (int q = 0; q < 4; q++) acc2[r][q] = 0ull;

    #pragma unroll
    for (int k = 0; k < 16; k++) {
        ulonglong2 B0 = *(const ulonglong2*)&sm.in.zjs[k][jb];
        ulonglong2 B1 = *(const ulonglong2*)&sm.in.zjs[k][jb + 4];
        #pragma unroll
        for (int r = 0; r < 8; r++) {
            u64 a2 = sm.in.zis[ib + r][k];
            acc2[r][0] = fma2(a2, B0.x, acc2[r][0]);
            acc2[r][1] = fma2(a2, B0.y, acc2[r][1]);
            acc2[r][2] = fma2(a2, B1.x, acc2[r][2]);
            acc2[r][3] = fma2(a2, B1.y, acc2[r][3]);
        }
    }

    // sigmoid in place (packed)
    #pragma unroll
    for (int r = 0; r < 8; r++)
        #pragma unroll
        for (int q = 0; q < 4; q++) acc2[r][q] = sig2(acc2[r][q]);

    // ---- normal write: out[i][j], coalesced float4 pairs ----
    int gjw = j0 + jb;
    #pragma unroll
    for (int r = 0; r < 8; r++) {
        int gi = i0 + ib + r;
        if (gi < NN && gjw < NN) {
            float4 o0 = make_float4(lo2(acc2[r][0]), hi2(acc2[r][0]),
                                    lo2(acc2[r][1]), hi2(acc2[r][1]));
            float4 o1 = make_float4(lo2(acc2[r][2]), hi2(acc2[r][2]),
                                    lo2(acc2[r][3]), hi2(acc2[r][3]));
            float* p = out + (size_t)gi * NN + gjw;
            *(float4*)p       = o0;
            *(float4*)(p + 4) = o1;
        }
    }

    if (bj == bi) return;   // diagonal tile: no mirror

    // ---- mirror write: out[j][i] via two 64-row transpose passes ----
    int warp = t >> 5, lane = t & 31;
    #pragma unroll
    for (int p = 0; p < 2; p++) {
        __syncthreads();    // pass 0: done reading zis/zjs; pass 1: done reading ts
        #pragma unroll
        for (int c = 0; c < 4; c++) {
            int cc   = (p << 2) + c;      // column within thread tile
            int q    = cc >> 1;
            int slot = (tx << 2) | c;     // 64 staging slots
            float4 v0, v1;
            if (cc & 1) {
                v0 = make_float4(hi2(acc2[0][q]), hi2(acc2[1][q]),
                                 hi2(acc2[2][q]), hi2(acc2[3][q]));
                v1 = make_float4(hi2(acc2[4][q]), hi2(acc2[5][q]),
                                 hi2(acc2[6][q]), hi2(acc2[7][q]));
            } else {
                v0 = make_float4(lo2(acc2[0][q]), lo2(acc2[1][q]),
                                 lo2(acc2[2][q]), lo2(acc2[3][q]));
                v1 = make_float4(lo2(acc2[4][q]), lo2(acc2[5][q]),
                                 lo2(acc2[6][q]), lo2(acc2[7][q]));
            }
            *(float4*)&sm.ts[slot][ib]     = v0;
            *(float4*)&sm.ts[slot][ib + 4] = v1;
        }
        __syncthreads();
        #pragma unroll
        for (int s8 = 0; s8 < 8; s8++) {
            int slot = (warp << 3) | s8;
            int jl   = ((slot >> 2) << 3) + (slot & 3) + (p << 2);
            int gj   = j0 + jl;
            int gi   = i0 + (lane << 2);
            if (gj < NN && gi < NN)
                *(float4*)(out + (size_t)gj * NN + gi) =
                    *(const float4*)&sm.ts[slot][lane << 2];
        }
    }
}

// ---------------- launch --------------------------------------------------
extern "C" void kernel_launch(void* const* d_in, const int* in_sizes, int n_in,
                              void* d_out, int out_size) {
    const float* x  = (const float*)d_in[0];
    const float* W1 = (const float*)d_in[1];
    const float* W2 = (const float*)d_in[2];
    const int*   ei = (const int*)  d_in[3];
    const float* ew = (const float*)d_in[4];

    float* out  = (float*)d_out;
    float* zout = out + (size_t)NN * NN;   // output layout: [adj (1e8) | z]

    k_zero <<<(NN + 255) / 256, 256>>>();
    k_build<<<(EE + 255) / 256, 256>>>(ei, ew);
    k_gemm1<<<(NN + 63) / 64, 256>>>(x, W1);
    k_spmm1<<<(NN * 32 + 255) / 256, 256>>>();
    k_gemm2<<<(NN + 255) / 256, 256>>>(W2);
    k_spmm2<<<(NN * 16 + 255) / 256, 256>>>(zout);

    dim3 gdec((NN + 127) / 128, (NN + 127) / 128);
    k_dec<<<gdec, 256>>>(zout, out);
}

// round 3
// speedup vs baseline: 1.1049x; 1.0660x over previous
#include <cuda_runtime.h>
#include <cstdint>

#define NN   10000
#define EE   320000
#define FIN  512
#define NHID 32
#define LAT  16
#define PAD  128
#define TT   79      // ceil(10000/128) tiles per dim
#define NTRI 3160    // TT*(TT+1)/2

typedef unsigned long long u64;

// ---------------- device scratch (no allocations allowed) ----------------
__device__ int   g_cnt[NN];
__device__ int   g_src[NN * PAD];
__device__ float g_wgt[NN * PAD];
__device__ float g_h0 [NN * NHID];
__device__ float g_h  [NN * NHID];
__device__ float g_z0 [NN * LAT];

// ---------------- f32x2 packed helpers (sm_103a FFMA2 path) --------------
__device__ __forceinline__ u64 fma2(u64 a, u64 b, u64 c) {
    u64 d;
    asm("fma.rn.f32x2 %0, %1, %2, %3;" : "=l"(d) : "l"(a), "l"(b), "l"(c));
    return d;
}
__device__ __forceinline__ u64 pack2(float x) {
    u64 d; asm("mov.b64 %0, {%1, %1};" : "=l"(d) : "f"(x)); return d;
}
__device__ __forceinline__ float lo2(u64 v) {
    float f; asm("{ .reg .f32 h; mov.b64 {%0, h}, %1; }" : "=f"(f) : "l"(v)); return f;
}
__device__ __forceinline__ float hi2(u64 v) {
    float f; asm("{ .reg .f32 l; mov.b64 {l, %0}, %1; }" : "=f"(f) : "l"(v)); return f;
}
__device__ __forceinline__ float sigmoid_fast(float x) {
    float t;
    asm("tanh.approx.f32 %0, %1;" : "=f"(t) : "f"(0.5f * x));
    return fmaf(0.5f, t, 0.5f);
}
__device__ __forceinline__ u64 sig2(u64 x) {
    float lo = sigmoid_fast(lo2(x));
    float hi = sigmoid_fast(hi2(x));
    u64 r; asm("mov.b64 %0, {%1, %2};" : "=l"(r) : "f"(lo), "f"(hi));
    return r;
}

// ---------------- adjacency build (padded, gather-friendly) --------------
__global__ void k_zero() {
    int i = blockIdx.x * blockDim.x + threadIdx.x;
    if (i < NN) g_cnt[i] = 0;
}

__global__ void k_build(const int* __restrict__ ei, const float* __restrict__ ew) {
    int e = blockIdx.x * blockDim.x + threadIdx.x;
    if (e >= EE) return;
    int   s = ei[e];
    int   d = ei[EE + e];
    float w = ew[e];
    int p = atomicAdd(&g_cnt[d], 1);
    if (p < PAD) {
        g_src[d * PAD + p] = s;
        g_wgt[d * PAD + p] = w;
    }
}

// ---------------- GEMM1: h0[N,32] = x[N,512] @ W1[512,32], FFMA2 ---------
__global__ void __launch_bounds__(256) k_gemm1(const float* __restrict__ x,
                                               const float* __restrict__ W1) {
    __shared__ float xs[64][28];
    __shared__ float w1s[16][32];

    int t    = threadIdx.x;
    int row0 = blockIdx.x * 64;
    int cg   = (t & 7) << 2;
    int rs   = (t >> 3) << 1;

    u64 a00 = 0ull, a01 = 0ull, a10 = 0ull, a11 = 0ull;  // (c,c+1)(c+2,c+3) x 2 rows

    for (int kk = 0; kk < FIN; kk += 16) {
        {
            int r  = t >> 2;
            int kq = (t & 3) << 2;
            int gr = row0 + r;
            float4 v = make_float4(0.f, 0.f, 0.f, 0.f);
            if (gr < NN) v = *(const float4*)(x + (size_t)gr * FIN + kk + kq);
            *(float4*)&xs[r][kq] = v;
        }
        if (t < 128) {
            int k = t >> 3, c = (t & 7) << 2;
            *(float4*)&w1s[k][c] = *(const float4*)(W1 + (size_t)(kk + k) * NHID + c);
        }
        __syncthreads();

        #pragma unroll
        for (int k = 0; k < 16; k++) {
            ulonglong2 bb = *(const ulonglong2*)&w1s[k][cg];
            u64 a0 = pack2(xs[rs][k]);
            u64 a1 = pack2(xs[rs + 1][k]);
            a00 = fma2(a0, bb.x, a00); a01 = fma2(a0, bb.y, a01);
            a10 = fma2(a1, bb.x, a10); a11 = fma2(a1, bb.y, a11);
        }
        __syncthreads();
    }

    int gr0 = row0 + rs;
    if (gr0 < NN)
        *(float4*)&g_h0[(size_t)gr0 * NHID + cg] =
            make_float4(lo2(a00), hi2(a00), lo2(a01), hi2(a01));
    if (gr0 + 1 < NN)
        *(float4*)&g_h0[(size_t)(gr0 + 1) * NHID + cg] =
            make_float4(lo2(a10), hi2(a10), lo2(a11), hi2(a11));
}

// ---------------- SpMM1: warp per node, vectorized index loads -----------
__global__ void __launch_bounds__(256) k_spmm1() {
    int gid  = blockIdx.x * blockDim.x + threadIdx.x;
    int d    = gid >> 5;
    int lane = gid & 31;
    if (d >= NN) return;
    int cnt = g_cnt[d];
    if (cnt > PAD) cnt = PAD;
    const int*   sp = &g_src[d * PAD];
    const float* wp = &g_wgt[d * PAD];
    float acc = 0.f;
    int j = 0;
    for (; j + 8 <= cnt; j += 8) {
        int4   s0 = *(const int4*)  (sp + j);
        int4   s1 = *(const int4*)  (sp + j + 4);
        float4 w0 = *(const float4*)(wp + j);
        float4 w1 = *(const float4*)(wp + j + 4);
        float v0 = g_h0[((size_t)s0.x << 5) + lane];
        float v1 = g_h0[((size_t)s0.y << 5) + lane];
        float v2 = g_h0[((size_t)s0.z << 5) + lane];
        float v3 = g_h0[((size_t)s0.w << 5) + lane];
        float v4 = g_h0[((size_t)s1.x << 5) + lane];
        float v5 = g_h0[((size_t)s1.y << 5) + lane];
        float v6 = g_h0[((size_t)s1.z << 5) + lane];
        float v7 = g_h0[((size_t)s1.w << 5) + lane];
        acc = fmaf(w0.x, v0, acc); acc = fmaf(w0.y, v1, acc);
        acc = fmaf(w0.z, v2, acc); acc = fmaf(w0.w, v3, acc);
        acc = fmaf(w1.x, v4, acc); acc = fmaf(w1.y, v5, acc);
        acc = fmaf(w1.z, v6, acc); acc = fmaf(w1.w, v7, acc);
    }
    for (; j < cnt; j++)
        acc = fmaf(wp[j], g_h0[((size_t)sp[j] << 5) + lane], acc);
    g_h[((size_t)d << 5) + lane] = acc;
}

// ---------------- GEMM2: z0[N,16] = h[N,32] @ W2[32,16] ------------------
__global__ void k_gemm2(const float* __restrict__ W2) {
    __shared__ float w2s[NHID * LAT];
    int t = threadIdx.x;
    for (int i = t; i < NHID * LAT; i += 256) w2s[i] = W2[i];
    __syncthreads();

    int row = blockIdx.x * 256 + t;
    if (row >= NN) return;

    float hr[NHID];
    #pragma unroll
    for (int q = 0; q < NHID / 4; q++) {
        float4 v = *(const float4*)&g_h[(size_t)row * NHID + q * 4];
        hr[q * 4 + 0] = v.x; hr[q * 4 + 1] = v.y;
        hr[q * 4 + 2] = v.z; hr[q * 4 + 3] = v.w;
    }
    #pragma unroll
    for (int c = 0; c < LAT; c++) {
        float acc = 0.f;
        #pragma unroll
        for (int k = 0; k < NHID; k++)
            acc = fmaf(hr[k], w2s[k * LAT + c], acc);
        g_z0[(size_t)row * LAT + c] = acc;
    }
}

// ---------------- SpMM2: 16 threads per node, vectorized -----------------
__global__ void __launch_bounds__(256) k_spmm2(float* __restrict__ zout) {
    int gid = blockIdx.x * blockDim.x + threadIdx.x;
    int d   = gid >> 4;
    int c   = gid & 15;
    if (d >= NN) return;
    int cnt = g_cnt[d];
    if (cnt > PAD) cnt = PAD;
    const int*   sp = &g_src[d * PAD];
    const float* wp = &g_wgt[d * PAD];
    float acc = 0.f;
    int j = 0;
    for (; j + 8 <= cnt; j += 8) {
        int4   s0 = *(const int4*)  (sp + j);
        int4   s1 = *(const int4*)  (sp + j + 4);
        float4 w0 = *(const float4*)(wp + j);
        float4 w1 = *(const float4*)(wp + j + 4);
        float v0 = g_z0[((size_t)s0.x << 4) + c];
        float v1 = g_z0[((size_t)s0.y << 4) + c];
        float v2 = g_z0[((size_t)s0.z << 4) + c];
        float v3 = g_z0[((size_t)s0.w << 4) + c];
        float v4 = g_z0[((size_t)s1.x << 4) + c];
        float v5 = g_z0[((size_t)s1.y << 4) + c];
        float v6 = g_z0[((size_t)s1.z << 4) + c];
        float v7 = g_z0[((size_t)s1.w << 4) + c];
        acc = fmaf(w0.x, v0, acc); acc = fmaf(w0.y, v1, acc);
        acc = fmaf(w0.z, v2, acc); acc = fmaf(w0.w, v3, acc);
        acc = fmaf(w1.x, v4, acc); acc = fmaf(w1.y, v5, acc);
        acc = fmaf(w1.z, v6, acc); acc = fmaf(w1.w, v7, acc);
    }
    for (; j < cnt; j++)
        acc = fmaf(wp[j], g_z0[((size_t)sp[j] << 4) + c], acc);
    zout[((size_t)d << 4) + c] = acc;
}

// ---------------- Decoder: adj = sigmoid(z @ z^T), symmetric -------------
// Linear triangular grid (3160 blocks). 128x128 tile, 8x8 per thread,
// packed FFMA2. zis is k-major packed u64 (pad 130): 4 broadcast LDS.128
// per k instead of 8 LDS.64. Mirror write via smem transpose.
// __launch_bounds__(256,2): 2 CTAs/SM so one CTA's store epilogue overlaps
// the other's mainloop. Output stores use streaming (evict-first) hint.
__global__ void __launch_bounds__(256, 2) k_dec(const float* __restrict__ z,
                                                float* __restrict__ out) {
    // triangular decode: b -> (bi, bj), bi <= bj
    int b  = blockIdx.x;
    int bi = (int)((159.0f - sqrtf(25281.0f - 8.0f * (float)b)) * 0.5f);
    // fix up float rounding
    while (((bi + 1) * TT - ((bi + 1) * bi) / 2) <= b) bi++;
    while ((bi * TT - (bi * (bi - 1)) / 2) > b) bi--;
    int bj = bi + (b - (bi * TT - (bi * (bi - 1)) / 2));

    __shared__ union SmU {
        struct {
            u64   zis[16][130];          // k-major packed (a,a), 16.25 KB
            float zjs[16][132];          // k-major, padded   8.25 KB
        } in;
        float ts[64][132];               // transpose staging 33.8 KB
    } sm;

    int t  = threadIdx.x;
    int i0 = bi * 128;
    int j0 = bj * 128;

    #pragma unroll
    for (int rep = 0; rep < 2; rep++) {
        int idx = t + rep * 256;
        int r   = idx >> 2;
        int kq  = (idx & 3) << 2;
        int gi  = i0 + r;
        float4 v = make_float4(0.f, 0.f, 0.f, 0.f);
        if (gi < NN) v = *(const float4*)(z + (size_t)gi * LAT + kq);
        sm.in.zis[kq + 0][r] = pack2(v.x);
        sm.in.zis[kq + 1][r] = pack2(v.y);
        sm.in.zis[kq + 2][r] = pack2(v.z);
        sm.in.zis[kq + 3][r] = pack2(v.w);

        int gj = j0 + r;
        float4 u = make_float4(0.f, 0.f, 0.f, 0.f);
        if (gj < NN) u = *(const float4*)(z + (size_t)gj * LAT + kq);
        sm.in.zjs[kq + 0][r] = u.x; sm.in.zjs[kq + 1][r] = u.y;
        sm.in.zjs[kq + 2][r] = u.z; sm.in.zjs[kq + 3][r] = u.w;
    }
    __syncthreads();

    int tx = t & 15, ty = t >> 4;
    int ib = ty << 3, jb = tx << 3;

    u64 acc2[8][4];
    #pragma unroll
    for (int r = 0; r < 8; r++)
        #pragma unroll
        for (int q = 0; q < 4; q++) acc2[r][q] = 0ull;

    #pragma unroll
    for (int k = 0; k < 16; k++) {
        ulonglong2 A0 = *(const ulonglong2*)&sm.in.zis[k][ib + 0];
        ulonglong2 A1 = *(const ulonglong2*)&sm.in.zis[k][ib + 2];
        ulonglong2 A2 = *(const ulonglong2*)&sm.in.zis[k][ib + 4];
        ulonglong2 A3 = *(const ulonglong2*)&sm.in.zis[k][ib + 6];
        ulonglong2 B0 = *(const ulonglong2*)&sm.in.zjs[k][jb];
        ulonglong2 B1 = *(const ulonglong2*)&sm.in.zjs[k][jb + 4];
        acc2[0][0] = fma2(A0.x, B0.x, acc2[0][0]);
        acc2[0][1] = fma2(A0.x, B0.y, acc2[0][1]);
        acc2[0][2] = fma2(A0.x, B1.x, acc2[0][2]);
        acc2[0][3] = fma2(A0.x, B1.y, acc2[0][3]);
        acc2[1][0] = fma2(A0.y, B0.x, acc2[1][0]);
        acc2[1][1] = fma2(A0.y, B0.y, acc2[1][1]);
        acc2[1][2] = fma2(A0.y, B1.x, acc2[1][2]);
        acc2[1][3] = fma2(A0.y, B1.y, acc2[1][3]);
        acc2[2][0] = fma2(A1.x, B0.x, acc2[2][0]);
        acc2[2][1] = fma2(A1.x, B0.y, acc2[2][1]);
        acc2[2][2] = fma2(A1.x, B1.x, acc2[2][2]);
        acc2[2][3] = fma2(A1.x, B1.y, acc2[2][3]);
        acc2[3][0] = fma2(A1.y, B0.x, acc2[3][0]);
        acc2[3][1] = fma2(A1.y, B0.y, acc2[3][1]);
        acc2[3][2] = fma2(A1.y, B1.x, acc2[3][2]);
        acc2[3][3] = fma2(A1.y, B1.y, acc2[3][3]);
        acc2[4][0] = fma2(A2.x, B0.x, acc2[4][0]);
        acc2[4][1] = fma2(A2.x, B0.y, acc2[4][1]);
        acc2[4][2] = fma2(A2.x, B1.x, acc2[4][2]);
        acc2[4][3] = fma2(A2.x, B1.y, acc2[4][3]);
        acc2[5][0] = fma2(A2.y, B0.x, acc2[5][0]);
        acc2[5][1] = fma2(A2.y, B0.y, acc2[5][1]);
        acc2[5][2] = fma2(A2.y, B1.x, acc2[5][2]);
        acc2[5][3] = fma2(A2.y, B1.y, acc2[5][3]);
        acc2[6][0] = fma2(A3.x, B0.x, acc2[6][0]);
        acc2[6][1] = fma2(A3.x, B0.y, acc2[6][1]);
        acc2[6][2] = fma2(A3.x, B1.x, acc2[6][2]);
        acc2[6][3] = fma2(A3.x, B1.y, acc2[6][3]);
        acc2[7][0] = fma2(A3.y, B0.x, acc2[7][0]);
        acc2[7][1] = fma2(A3.y, B0.y, acc2[7][1]);
        acc2[7][2] = fma2(A3.y, B1.x, acc2[7][2]);
        acc2[7][3] = fma2(A3.y, B1.y, acc2[7][3]);
    }

    // sigmoid in place (packed)
    #pragma unroll
    for (int r = 0; r < 8; r++)
        #pragma unroll
        for (int q = 0; q < 4; q++) acc2[r][q] = sig2(acc2[r][q]);

    // ---- normal write: out[i][j], streaming float4 ----
    int gjw = j0 + jb;
    #pragma unroll
    for (int r = 0; r < 8; r++) {
        int gi = i0 + ib + r;
        if (gi < NN && gjw < NN) {
            float4 o0 = make_float4(lo2(acc2[r][0]), hi2(acc2[r][0]),
                                    lo2(acc2[r][1]), hi2(acc2[r][1]));
            float4 o1 = make_float4(lo2(acc2[r][2]), hi2(acc2[r][2]),
                                    lo2(acc2[r][3]), hi2(acc2[r][3]));
            float* p = out + (size_t)gi * NN + gjw;
            __stcs((float4*)p, o0);
            __stcs((float4*)(p + 4), o1);
        }
    }

    if (bj == bi) return;   // diagonal tile: no mirror

    // ---- mirror write: out[j][i] via two 64-row transpose passes ----
    int warp = t >> 5, lane = t & 31;
    #pragma unroll
    for (int p = 0; p < 2; p++) {
        __syncthreads();    // pass 0: done reading zis/zjs; pass 1: done reading ts
        #pragma unroll
        for (int c = 0; c < 4; c++) {
            int cc   = (p << 2) + c;
            int q    = cc >> 1;
            int slot = (tx << 2) | c;
            float4 v0, v1;
            if (cc & 1) {
                v0 = make_float4(hi2(acc2[0][q]), hi2(acc2[1][q]),
                                 hi2(acc2[2][q]), hi2(acc2[3][q]));
                v1 = make_float4(hi2(acc2[4][q]), hi2(acc2[5][q]),
                                 hi2(acc2[6][q]), hi2(acc2[7][q]));
            } else {
                v0 = make_float4(lo2(acc2[0][q]), lo2(acc2[1][q]),
                                 lo2(acc2[2][q]), lo2(acc2[3][q]));
                v1 = make_float4(lo2(acc2[4][q]), lo2(acc2[5][q]),
                                 lo2(acc2[6][q]), lo2(acc2[7][q]));
            }
            *(float4*)&sm.ts[slot][ib]     = v0;
            *(float4*)&sm.ts[slot][ib + 4] = v1;
        }
        __syncthreads();
        #pragma unroll
        for (int s8 = 0; s8 < 8; s8++) {
            int slot = (warp << 3) | s8;
            int jl   = ((slot >> 2) << 3) + (slot & 3) + (p << 2);
            int gj   = j0 + jl;
            int gi   = i0 + (lane << 2);
            if (gj < NN && gi < NN)
                __stcs((float4*)(out + (size_t)gj * NN + gi),
                       *(const float4*)&sm.ts[slot][lane << 2]);
        }
    }
}

// ---------------- launch --------------------------------------------------
extern "C" void kernel_launch(void* const* d_in, const int* in_sizes, int n_in,
                              void* d_out, int out_size) {
    const float* x  = (const float*)d_in[0];
    const float* W1 = (const float*)d_in[1];
    const float* W2 = (const float*)d_in[2];
    const int*   ei = (const int*)  d_in[3];
    const float* ew = (const float*)d_in[4];

    float* out  = (float*)d_out;
    float* zout = out + (size_t)NN * NN;   // output layout: [adj (1e8) | z]

    k_zero <<<(NN + 255) / 256, 256>>>();
    k_build<<<(EE + 255) / 256, 256>>>(ei, ew);
    k_gemm1<<<(NN + 63) / 64, 256>>>(x, W1);
    k_spmm1<<<(NN * 32 + 255) / 256, 256>>>();
    k_gemm2<<<(NN + 255) / 256, 256>>>(W2);
    k_spmm2<<<(NN * 16 + 255) / 256, 256>>>(zout);

    k_dec<<<NTRI, 256>>>(zout, out);
}

// round 4
// speedup vs baseline: 1.1702x; 1.0592x over previous
#include <cuda_runtime.h>
#include <cstdint>

#define NN   10000
#define EE   320000
#define FIN  512
#define NHID 32
#define LAT  16
#define PAD  128
#define TT   79      // ceil(10000/128) tiles per dim
#define NTRI 3160    // TT*(TT+1)/2

typedef unsigned long long u64;

// ---------------- device scratch (no allocations allowed) ----------------
__device__ int   g_cnt[NN];
__device__ int   g_src[NN * PAD];
__device__ float g_wgt[NN * PAD];
__device__ float g_h0 [NN * NHID];
__device__ float g_z0 [NN * LAT];

// ---------------- f32x2 packed helpers (sm_103a FFMA2 path) --------------
__device__ __forceinline__ u64 fma2(u64 a, u64 b, u64 c) {
    u64 d;
    asm("fma.rn.f32x2 %0, %1, %2, %3;" : "=l"(d) : "l"(a), "l"(b), "l"(c));
    return d;
}
__device__ __forceinline__ u64 pack2(float x) {
    u64 d; asm("mov.b64 %0, {%1, %1};" : "=l"(d) : "f"(x)); return d;
}
__device__ __forceinline__ float lo2(u64 v) {
    float f; asm("{ .reg .f32 h; mov.b64 {%0, h}, %1; }" : "=f"(f) : "l"(v)); return f;
}
__device__ __forceinline__ float hi2(u64 v) {
    float f; asm("{ .reg .f32 l; mov.b64 {l, %0}, %1; }" : "=f"(f) : "l"(v)); return f;
}
__device__ __forceinline__ float sigmoid_fast(float x) {
    float t;
    asm("tanh.approx.f32 %0, %1;" : "=f"(t) : "f"(0.5f * x));
    return fmaf(0.5f, t, 0.5f);
}
__device__ __forceinline__ u64 sig2(u64 x) {
    float lo = sigmoid_fast(lo2(x));
    float hi = sigmoid_fast(hi2(x));
    u64 r; asm("mov.b64 %0, {%1, %2};" : "=l"(r) : "f"(lo), "f"(hi));
    return r;
}

// ---------------- adjacency build (padded, gather-friendly) --------------
__global__ void k_zero() {
    int i = blockIdx.x * blockDim.x + threadIdx.x;
    if (i < NN) g_cnt[i] = 0;
}

__global__ void k_build(const int* __restrict__ ei, const float* __restrict__ ew) {
    int e = blockIdx.x * blockDim.x + threadIdx.x;
    if (e >= EE) return;
    int   s = ei[e];
    int   d = ei[EE + e];
    float w = ew[e];
    int p = atomicAdd(&g_cnt[d], 1);
    if (p < PAD) {
        g_src[d * PAD + p] = s;
        g_wgt[d * PAD + p] = w;
    }
}

// ---------------- GEMM1: h0[N,32] = x[N,512] @ W1[512,32], FFMA2 ---------
__global__ void __launch_bounds__(256) k_gemm1(const float* __restrict__ x,
                                               const float* __restrict__ W1) {
    __shared__ float xs[64][28];
    __shared__ float w1s[16][32];

    int t    = threadIdx.x;
    int row0 = blockIdx.x * 64;
    int cg   = (t & 7) << 2;
    int rs   = (t >> 3) << 1;

    u64 a00 = 0ull, a01 = 0ull, a10 = 0ull, a11 = 0ull;

    for (int kk = 0; kk < FIN; kk += 16) {
        {
            int r  = t >> 2;
            int kq = (t & 3) << 2;
            int gr = row0 + r;
            float4 v = make_float4(0.f, 0.f, 0.f, 0.f);
            if (gr < NN) v = *(const float4*)(x + (size_t)gr * FIN + kk + kq);
            *(float4*)&xs[r][kq] = v;
        }
        if (t < 128) {
            int k = t >> 3, c = (t & 7) << 2;
            *(float4*)&w1s[k][c] = *(const float4*)(W1 + (size_t)(kk + k) * NHID + c);
        }
        __syncthreads();

        #pragma unroll
        for (int k = 0; k < 16; k++) {
            ulonglong2 bb = *(const ulonglong2*)&w1s[k][cg];
            u64 a0 = pack2(xs[rs][k]);
            u64 a1 = pack2(xs[rs + 1][k]);
            a00 = fma2(a0, bb.x, a00); a01 = fma2(a0, bb.y, a01);
            a10 = fma2(a1, bb.x, a10); a11 = fma2(a1, bb.y, a11);
        }
        __syncthreads();
    }

    int gr0 = row0 + rs;
    if (gr0 < NN)
        *(float4*)&g_h0[(size_t)gr0 * NHID + cg] =
            make_float4(lo2(a00), hi2(a00), lo2(a01), hi2(a01));
    if (gr0 + 1 < NN)
        *(float4*)&g_h0[(size_t)(gr0 + 1) * NHID + cg] =
            make_float4(lo2(a10), hi2(a10), lo2(a11), hi2(a11));
}

// ------- Fused SpMM1 + GEMM2: z0[d,:] = (sum_e w_e*h0[src_e,:]) @ W2 -----
// Warp per node: lane holds h[d,lane] after the gather; then 32 shfl
// broadcasts x 32 FMAs compute the 16 output columns in-register.
__global__ void __launch_bounds__(256) k_spmm1_gemm2(const float* __restrict__ W2) {
    __shared__ float w2s[NHID * LAT];
    {
        int t = threadIdx.x;
        for (int i = t; i < NHID * LAT; i += 256) w2s[i] = W2[i];
    }
    __syncthreads();

    int gid  = blockIdx.x * blockDim.x + threadIdx.x;
    int d    = gid >> 5;
    int lane = gid & 31;
    if (d >= NN) return;
    int cnt = g_cnt[d];
    if (cnt > PAD) cnt = PAD;
    const int*   sp = &g_src[d * PAD];
    const float* wp = &g_wgt[d * PAD];
    float acc = 0.f;
    int j = 0;
    for (; j + 8 <= cnt; j += 8) {
        int4   s0 = *(const int4*)  (sp + j);
        int4   s1 = *(const int4*)  (sp + j + 4);
        float4 w0 = *(const float4*)(wp + j);
        float4 w1 = *(const float4*)(wp + j + 4);
        float v0 = g_h0[((size_t)s0.x << 5) + lane];
        float v1 = g_h0[((size_t)s0.y << 5) + lane];
        float v2 = g_h0[((size_t)s0.z << 5) + lane];
        float v3 = g_h0[((size_t)s0.w << 5) + lane];
        float v4 = g_h0[((size_t)s1.x << 5) + lane];
        float v5 = g_h0[((size_t)s1.y << 5) + lane];
        float v6 = g_h0[((size_t)s1.z << 5) + lane];
        float v7 = g_h0[((size_t)s1.w << 5) + lane];
        acc = fmaf(w0.x, v0, acc); acc = fmaf(w0.y, v1, acc);
        acc = fmaf(w0.z, v2, acc); acc = fmaf(w0.w, v3, acc);
        acc = fmaf(w1.x, v4, acc); acc = fmaf(w1.y, v5, acc);
        acc = fmaf(w1.z, v6, acc); acc = fmaf(w1.w, v7, acc);
    }
    for (; j < cnt; j++)
        acc = fmaf(wp[j], g_h0[((size_t)sp[j] << 5) + lane], acc);

    // h[d,:] now distributed across lanes; compute z0[d,c] for c = lane&15
    int c = lane & 15;
    float zc = 0.f;
    #pragma unroll
    for (int k = 0; k < NHID; k++) {
        float hk = __shfl_sync(0xffffffffu, acc, k);
        zc = fmaf(hk, w2s[k * LAT + c], zc);
    }
    if (lane < LAT)
        g_z0[((size_t)d << 4) + c] = zc;
}

// ---------------- SpMM2: 16 threads per node, vectorized -----------------
__global__ void __launch_bounds__(256) k_spmm2(float* __restrict__ zout) {
    int gid = blockIdx.x * blockDim.x + threadIdx.x;
    int d   = gid >> 4;
    int c   = gid & 15;
    if (d >= NN) return;
    int cnt = g_cnt[d];
    if (cnt > PAD) cnt = PAD;
    const int*   sp = &g_src[d * PAD];
    const float* wp = &g_wgt[d * PAD];
    float acc = 0.f;
    int j = 0;
    for (; j + 8 <= cnt; j += 8) {
        int4   s0 = *(const int4*)  (sp + j);
        int4   s1 = *(const int4*)  (sp + j + 4);
        float4 w0 = *(const float4*)(wp + j);
        float4 w1 = *(const float4*)(wp + j + 4);
        float v0 = g_z0[((size_t)s0.x << 4) + c];
        float v1 = g_z0[((size_t)s0.y << 4) + c];
        float v2 = g_z0[((size_t)s0.z << 4) + c];
        float v3 = g_z0[((size_t)s0.w << 4) + c];
        float v4 = g_z0[((size_t)s1.x << 4) + c];
        float v5 = g_z0[((size_t)s1.y << 4) + c];
        float v6 = g_z0[((size_t)s1.z << 4) + c];
        float v7 = g_z0[((size_t)s1.w << 4) + c];
        acc = fmaf(w0.x, v0, acc); acc = fmaf(w0.y, v1, acc);
        acc = fmaf(w0.z, v2, acc); acc = fmaf(w0.w, v3, acc);
        acc = fmaf(w1.x, v4, acc); acc = fmaf(w1.y, v5, acc);
        acc = fmaf(w1.z, v6, acc); acc = fmaf(w1.w, v7, acc);
    }
    for (; j < cnt; j++)
        acc = fmaf(wp[j], g_z0[((size_t)sp[j] << 4) + c], acc);
    zout[((size_t)d << 4) + c] = acc;
}

// ---------------- Decoder: adj = sigmoid(z @ z^T), symmetric -------------
// Triangular grid; 128x128 tile; 8x8 per thread; FFMA2.
// Both z tiles k-major float. Per k: 2 LDS.128 for A (8 rows) duplicated
// in-register via ALU mov.b64 {x,x} (off the LSU pipe), 2 LDS.128 for B.
// Mirror via smem transpose; streaming stores.
__global__ void __launch_bounds__(256, 2) k_dec(const float* __restrict__ z,
                                                float* __restrict__ out) {
    int b  = blockIdx.x;
    int bi = (int)((159.0f - sqrtf(25281.0f - 8.0f * (float)b)) * 0.5f);
    while (((bi + 1) * TT - ((bi + 1) * bi) / 2) <= b) bi++;
    while ((bi * TT - (bi * (bi - 1)) / 2) > b) bi--;
    int bj = bi + (b - (bi * TT - (bi * (bi - 1)) / 2));

    __shared__ union SmU {
        struct {
            float zis[16][132];          // k-major, 8.25 KB
            float zjs[16][132];          // k-major, 8.25 KB
        } in;
        float ts[64][132];               // transpose staging 33.8 KB
    } sm;

    int t  = threadIdx.x;
    int i0 = bi * 128;
    int j0 = bj * 128;

    #pragma unroll
    for (int rep = 0; rep < 2; rep++) {
        int idx = t + rep * 256;
        int r   = idx >> 2;
        int kq  = (idx & 3) << 2;
        int gi  = i0 + r;
        float4 v = make_float4(0.f, 0.f, 0.f, 0.f);
        if (gi < NN) v = *(const float4*)(z + (size_t)gi * LAT + kq);
        sm.in.zis[kq + 0][r] = v.x; sm.in.zis[kq + 1][r] = v.y;
        sm.in.zis[kq + 2][r] = v.z; sm.in.zis[kq + 3][r] = v.w;

        int gj = j0 + r;
        float4 u = make_float4(0.f, 0.f, 0.f, 0.f);
        if (gj < NN) u = *(const float4*)(z + (size_t)gj * LAT + kq);
        sm.in.zjs[kq + 0][r] = u.x; sm.in.zjs[kq + 1][r] = u.y;
        sm.in.zjs[kq + 2][r] = u.z; sm.in.zjs[kq + 3][r] = u.w;
    }
    __syncthreads();

    int tx = t & 15, ty = t >> 4;
    int ib = ty << 3, jb = tx << 3;

    u64 acc2[8][4];
    #pragma unroll
    for (int r = 0; r < 8; r++)
        #pragma unroll
        for (int q = 0; q < 4; q++) acc2[r][q] = 0ull;

    #pragma unroll
    for (int k = 0; k < 16; k++) {
        float4 a0 = *(const float4*)&sm.in.zis[k][ib];       // rows ib..ib+3 (broadcast)
        float4 a1 = *(const float4*)&sm.in.zis[k][ib + 4];
        ulonglong2 B0 = *(const ulonglong2*)&sm.in.zjs[k][jb];      // (b0,b1)(b2,b3)
        ulonglong2 B1 = *(const ulonglong2*)&sm.in.zjs[k][jb + 4];  // (b4,b5)(b6,b7)
        u64 A[8];
        A[0] = pack2(a0.x); A[1] = pack2(a0.y); A[2] = pack2(a0.z); A[3] = pack2(a0.w);
        A[4] = pack2(a1.x); A[5] = pack2(a1.y); A[6] = pack2(a1.z); A[7] = pack2(a1.w);
        #pragma unroll
        for (int r = 0; r < 8; r++) {
            acc2[r][0] = fma2(A[r], B0.x, acc2[r][0]);
            acc2[r][1] = fma2(A[r], B0.y, acc2[r][1]);
            acc2[r][2] = fma2(A[r], B1.x, acc2[r][2]);
            acc2[r][3] = fma2(A[r], B1.y, acc2[r][3]);
        }
    }

    #pragma unroll
    for (int r = 0; r < 8; r++)
        #pragma unroll
        for (int q = 0; q < 4; q++) acc2[r][q] = sig2(acc2[r][q]);

    // ---- normal write: out[i][j], streaming float4 ----
    int gjw = j0 + jb;
    #pragma unroll
    for (int r = 0; r < 8; r++) {
        int gi = i0 + ib + r;
        if (gi < NN && gjw < NN) {
            float4 o0 = make_float4(lo2(acc2[r][0]), hi2(acc2[r][0]),
                                    lo2(acc2[r][1]), hi2(acc2[r][1]));
            float4 o1 = make_float4(lo2(acc2[r][2]), hi2(acc2[r][2]),
                                    lo2(acc2[r][3]), hi2(acc2[r][3]));
            float* p = out + (size_t)gi * NN + gjw;
            __stcs((float4*)p, o0);
            __stcs((float4*)(p + 4), o1);
        }
    }

    if (bj == bi) return;

    // ---- mirror write: out[j][i] via two 64-row transpose passes ----
    int warp = t >> 5, lane = t & 31;
    #pragma unroll
    for (int p = 0; p < 2; p++) {
        __syncthreads();
        #pragma unroll
        for (int c = 0; c < 4; c++) {
            int cc   = (p << 2) + c;
            int q    = cc >> 1;
            int slot = (tx << 2) | c;
            float4 v0, v1;
            if (cc & 1) {
                v0 = make_float4(hi2(acc2[0][q]), hi2(acc2[1][q]),
                                 hi2(acc2[2][q]), hi2(acc2[3][q]));
                v1 = make_float4(hi2(acc2[4][q]), hi2(acc2[5][q]),
                                 hi2(acc2[6][q]), hi2(acc2[7][q]));
            } else {
                v0 = make_float4(lo2(acc2[0][q]), lo2(acc2[1][q]),
                                 lo2(acc2[2][q]), lo2(acc2[3][q]));
                v1 = make_float4(lo2(acc2[4][q]), lo2(acc2[5][q]),
                                 lo2(acc2[6][q]), lo2(acc2[7][q]));
            }
            *(float4*)&sm.ts[slot][ib]     = v0;
            *(float4*)&sm.ts[slot][ib + 4] = v1;
        }
        __syncthreads();
        #pragma unroll
        for (int s8 = 0; s8 < 8; s8++) {
            int slot = (warp << 3) | s8;
            int jl   = ((slot >> 2) << 3) + (slot & 3) + (p << 2);
            int gj   = j0 + jl;
            int gi   = i0 + (lane << 2);
            if (gj < NN && gi < NN)
                __stcs((float4*)(out + (size_t)gj * NN + gi),
                       *(const float4*)&sm.ts[slot][lane << 2]);
        }
    }
}

// ---------------- launch --------------------------------------------------
extern "C" void kernel_launch(void* const* d_in, const int* in_sizes, int n_in,
                              void* d_out, int out_size) {
    const float* x  = (const float*)d_in[0];
    const float* W1 = (const float*)d_in[1];
    const float* W2 = (const float*)d_in[2];
    const int*   ei = (const int*)  d_in[3];
    const float* ew = (const float*)d_in[4];

    float* out  = (float*)d_out;
    float* zout = out + (size_t)NN * NN;   // output layout: [adj (1e8) | z]

    k_zero       <<<(NN + 255) / 256, 256>>>();
    k_build      <<<(EE + 255) / 256, 256>>>(ei, ew);
    k_gemm1      <<<(NN + 63) / 64, 256>>>(x, W1);
    k_spmm1_gemm2<<<(NN * 32 + 255) / 256, 256>>>(W2);
    k_spmm2      <<<(NN * 16 + 255) / 256, 256>>>(zout);
    k_dec        <<<NTRI, 256>>>(zout, out);
}